// round 3
// baseline (speedup 1.0000x reference)
#include <cuda_runtime.h>
#include <cuda_fp16.h>
#include <cstdint>

// Problem sizes (fixed by the dataset)
#define TOK 32768
#define DD  1024
#define UU  1024

// ---------------- scratch (device globals; no allocs allowed) ----------------
__device__ __align__(1024) __half g_xq[(size_t)TOK * DD];   // sign(x) as fp16 +/-1, [TOK, DD] row-major
__device__ __align__(1024) __half g_wt[(size_t)UU * DD];    // W_comb transposed: [U, D] K-major fp16
__device__ float g_beta[TOK];

// ---------------- helpers ----------------
__device__ __forceinline__ uint32_t smem_u32(const void* p) {
    uint32_t a;
    asm("{ .reg .u64 t; cvta.to.shared.u64 t, %1; cvt.u32.u64 %0, t; }" : "=r"(a) : "l"(p));
    return a;
}
__device__ __forceinline__ void cp16(uint32_t dst, const void* src) {
    asm volatile("cp.async.cg.shared.global [%0], [%1], 16;" :: "r"(dst), "l"(src));
}
__device__ __forceinline__ uint32_t swz(uint32_t row, uint32_t chunk) {
    // 128B rows, 8 x 16B chunks, XOR swizzle for conflict-free ldmatrix
    return row * 128u + ((chunk ^ (row & 7u)) * 16u);
}
__device__ __forceinline__ void ldsm4(uint32_t& r0, uint32_t& r1, uint32_t& r2, uint32_t& r3, uint32_t addr) {
    asm volatile("ldmatrix.sync.aligned.m8n8.x4.shared.b16 {%0,%1,%2,%3}, [%4];"
        : "=r"(r0), "=r"(r1), "=r"(r2), "=r"(r3) : "r"(addr));
}
__device__ __forceinline__ void mma16816(float* d, const uint32_t* a, const uint32_t* b) {
    asm volatile(
        "mma.sync.aligned.m16n8k16.row.col.f32.f16.f16.f32 "
        "{%0,%1,%2,%3}, {%4,%5,%6,%7}, {%8,%9}, {%0,%1,%2,%3};"
        : "+f"(d[0]), "+f"(d[1]), "+f"(d[2]), "+f"(d[3])
        : "r"(a[0]), "r"(a[1]), "r"(a[2]), "r"(a[3]), "r"(b[0]), "r"(b[1]));
}

// ---------------- kernel 1: quantize x, compute beta ----------------
__device__ __forceinline__ uint32_t sign_h(float v) {
    return v >= 0.0f ? 0x3C00u : 0xBC00u;   // +1.0h / -1.0h
}

__global__ __launch_bounds__(128) void prep_x_kernel(const float* __restrict__ x) {
    int row = blockIdx.x;
    int t = threadIdx.x;  // 128 threads, 8 floats each
    const float4* xr = reinterpret_cast<const float4*>(x + (size_t)row * DD);
    float4 a = xr[2 * t];
    float4 b = xr[2 * t + 1];
    float s = fabsf(a.x) + fabsf(a.y) + fabsf(a.z) + fabsf(a.w)
            + fabsf(b.x) + fabsf(b.y) + fabsf(b.z) + fabsf(b.w);

    uint4 pk;
    pk.x = sign_h(a.x) | (sign_h(a.y) << 16);
    pk.y = sign_h(a.z) | (sign_h(a.w) << 16);
    pk.z = sign_h(b.x) | (sign_h(b.y) << 16);
    pk.w = sign_h(b.z) | (sign_h(b.w) << 16);
    reinterpret_cast<uint4*>(g_xq)[(size_t)row * 128 + t] = pk;

    #pragma unroll
    for (int o = 16; o > 0; o >>= 1) s += __shfl_xor_sync(0xFFFFFFFFu, s, o);
    __shared__ float ws[4];
    if ((t & 31) == 0) ws[t >> 5] = s;
    __syncthreads();
    if (t == 0) g_beta[row] = (ws[0] + ws[1] + ws[2] + ws[3]) * (1.0f / 1024.0f);
}

// ---------------- kernel 2: combined weight, transposed to [U, D] ----------------
__global__ __launch_bounds__(1024) void prep_w_kernel(
    const float* __restrict__ k0, const float* __restrict__ k1, const float* __restrict__ k2,
    const float* __restrict__ a0, const float* __restrict__ a1, const float* __restrict__ a2)
{
    __shared__ float tile[32][33];
    int tx = threadIdx.x, ty = threadIdx.y;
    int u = blockIdx.x * 32 + tx;
    int d = blockIdx.y * 32 + ty;
    float A0 = a0[u], A1 = a1[u], A2 = a2[u];
    size_t idx = (size_t)d * UU + u;
    float w = (k0[idx] >= 0.0f ? A0 : -A0)
            + (k1[idx] >= 0.0f ? A1 : -A1)
            + (k2[idx] >= 0.0f ? A2 : -A2);
    tile[ty][tx] = w;
    __syncthreads();
    int uo = blockIdx.x * 32 + ty;
    int dd = blockIdx.y * 32 + tx;
    g_wt[(size_t)uo * DD + dd] = __float2half(tile[tx][ty]);
}

// ---------------- kernel 3: HMMA GEMM (mma.sync) + beta-scale epilogue ----------------
// C[m, u] = sign(x)[m, :] . W_comb[:, u];  out = beta[m] * C
// CTA tile 128x256, K-chunk 64, 3-stage cp.async pipeline, 16 warps (warp tile 32x64).
static constexpr int BM = 128, BN = 256, BK = 64;
static constexpr int STAGES = 3;
static constexpr int A_BYTES = BM * BK * 2;              // 16384
static constexpr int B_BYTES = BN * BK * 2;              // 32768
static constexpr int STG_BYTES = A_BYTES + B_BYTES;      // 49152
static constexpr int SMEM_TOTAL = STAGES * STG_BYTES;    // 147456
static constexpr int KITERS = DD / BK;                   // 16

__device__ __forceinline__ void load_stage(uint32_t sbase, int stage, int m0, int n0, int kb, int tid) {
    uint32_t sa  = sbase + (uint32_t)stage * STG_BYTES;
    uint32_t sbb = sa + A_BYTES;
    const char* gA = reinterpret_cast<const char*>(g_xq + (size_t)m0 * DD + kb);
    const char* gB = reinterpret_cast<const char*>(g_wt + (size_t)n0 * DD + kb);
    // A: 128 rows x 8 chunks of 16B = 1024 chunks, 512 threads -> 2 each
    #pragma unroll
    for (int i = 0; i < 2; i++) {
        int idx = tid + i * 512;
        uint32_t r = (uint32_t)idx >> 3, c = (uint32_t)idx & 7;
        cp16(sa + swz(r, c), gA + (size_t)r * (DD * 2) + c * 16);
    }
    // B: 256 rows x 8 chunks = 2048 chunks -> 4 each
    #pragma unroll
    for (int i = 0; i < 4; i++) {
        int idx = tid + i * 512;
        uint32_t r = (uint32_t)idx >> 3, c = (uint32_t)idx & 7;
        cp16(sbb + swz(r, c), gB + (size_t)r * (DD * 2) + c * 16);
    }
}

__global__ __launch_bounds__(512, 1) void gemm_kernel(float* __restrict__ out) {
    extern __shared__ char smem[];
    uint32_t sb = smem_u32(smem);
    int tid = threadIdx.x;
    int wid = tid >> 5, lane = tid & 31;
    int m0 = (int)(blockIdx.x >> 2) * BM;   // 256 m-tiles
    int n0 = (int)(blockIdx.x & 3) * BN;    // 4 n-tiles
    int wrow = (wid & 3) * 32;              // warp m-origin within CTA
    int wcol = (wid >> 2) * 64;             // warp n-origin within CTA

    // prologue: stages 0, 1
    load_stage(sb, 0, m0, n0, 0, tid);
    asm volatile("cp.async.commit_group;" ::: "memory");
    load_stage(sb, 1, m0, n0, BK, tid);
    asm volatile("cp.async.commit_group;" ::: "memory");

    float acc[2][8][4];
    #pragma unroll
    for (int i = 0; i < 2; i++)
        #pragma unroll
        for (int j = 0; j < 8; j++)
            #pragma unroll
            for (int k = 0; k < 4; k++) acc[i][j][k] = 0.0f;

    for (int it = 0; it < KITERS; ++it) {
        asm volatile("cp.async.wait_group 1;" ::: "memory");
        __syncthreads();
        // refill oldest stage (consumed in iteration it-1; ordered by the barrier)
        if (it + 2 < KITERS)
            load_stage(sb, (it + 2) % STAGES, m0, n0, (it + 2) * BK, tid);
        asm volatile("cp.async.commit_group;" ::: "memory");

        uint32_t sa  = sb + (uint32_t)(it % STAGES) * STG_BYTES;
        uint32_t sbb = sa + A_BYTES;

        #pragma unroll
        for (int k16 = 0; k16 < 4; k16++) {
            uint32_t a[2][4], b[4][4];
            #pragma unroll
            for (int mb = 0; mb < 2; mb++) {
                uint32_t row = (uint32_t)(wrow + mb * 16 + (lane & 15));
                uint32_t ch  = (uint32_t)(k16 * 2 + (lane >> 4));
                ldsm4(a[mb][0], a[mb][1], a[mb][2], a[mb][3], sa + swz(row, ch));
            }
            #pragma unroll
            for (int nb16 = 0; nb16 < 4; nb16++) {
                uint32_t row = (uint32_t)(wcol + nb16 * 16 + (lane & 7) + (lane >> 4) * 8);
                uint32_t ch  = (uint32_t)(k16 * 2 + ((lane >> 3) & 1));
                ldsm4(b[nb16][0], b[nb16][1], b[nb16][2], b[nb16][3], sbb + swz(row, ch));
            }
            #pragma unroll
            for (int mb = 0; mb < 2; mb++)
                #pragma unroll
                for (int nb = 0; nb < 8; nb++)
                    mma16816(acc[mb][nb], a[mb], &b[nb >> 1][(nb & 1) * 2]);
        }
    }

    // epilogue: scale rows by beta and store
    int group = lane >> 2, t4 = lane & 3;
    #pragma unroll
    for (int mb = 0; mb < 2; mb++) {
        int r0 = m0 + wrow + mb * 16 + group;
        float b0 = g_beta[r0];
        float b1 = g_beta[r0 + 8];
        float* o0 = out + (size_t)r0 * UU + n0 + wcol + t4 * 2;
        float* o1 = o0 + (size_t)8 * UU;
        #pragma unroll
        for (int nb = 0; nb < 8; nb++) {
            float2 v0 = make_float2(acc[mb][nb][0] * b0, acc[mb][nb][1] * b0);
            float2 v1 = make_float2(acc[mb][nb][2] * b1, acc[mb][nb][3] * b1);
            *reinterpret_cast<float2*>(o0 + nb * 8) = v0;
            *reinterpret_cast<float2*>(o1 + nb * 8) = v1;
        }
    }
}

// ---------------- launch ----------------
extern "C" void kernel_launch(void* const* d_in, const int* in_sizes, int n_in,
                              void* d_out, int out_size) {
    const float* x  = (const float*)d_in[0];
    const float* k0 = (const float*)d_in[1];
    const float* k1 = (const float*)d_in[2];
    const float* k2 = (const float*)d_in[3];
    const float* a0 = (const float*)d_in[4];
    const float* a1 = (const float*)d_in[5];
    const float* a2 = (const float*)d_in[6];
    float* out = (float*)d_out;

    prep_x_kernel<<<TOK, 128>>>(x);
    prep_w_kernel<<<dim3(UU / 32, DD / 32), dim3(32, 32)>>>(k0, k1, k2, a0, a1, a2);

    cudaFuncSetAttribute(gemm_kernel, cudaFuncAttributeMaxDynamicSharedMemorySize, SMEM_TOTAL);
    gemm_kernel<<<(TOK / BM) * (UU / BN), 512, SMEM_TOTAL>>>(out);
}

// round 4
// speedup vs baseline: 1.0017x; 1.0017x over previous
#include <cuda_runtime.h>
#include <cuda_fp16.h>
#include <cstdint>

// Problem sizes (fixed by the dataset)
#define TOK 32768
#define DD  1024
#define UU  1024

// ---------------- scratch (device globals; no allocs allowed) ----------------
__device__ __align__(1024) __half g_xq[(size_t)TOK * DD];   // sign(x) as fp16 +/-1, [TOK, DD] row-major
__device__ __align__(1024) __half g_wt[(size_t)UU * DD];    // W_comb transposed: [U, D] K-major fp16
__device__ float g_beta[TOK];

// ---------------- helpers ----------------
__device__ __forceinline__ uint32_t smem_u32(const void* p) {
    uint32_t a;
    asm("{ .reg .u64 t; cvta.to.shared.u64 t, %1; cvt.u32.u64 %0, t; }" : "=r"(a) : "l"(p));
    return a;
}
__device__ __forceinline__ void cp16(uint32_t dst, const void* src) {
    asm volatile("cp.async.cg.shared.global [%0], [%1], 16;" :: "r"(dst), "l"(src));
}
__device__ __forceinline__ uint32_t swz(uint32_t row, uint32_t chunk) {
    // 128B rows, 8 x 16B chunks, XOR swizzle for conflict-free ldmatrix
    return row * 128u + ((chunk ^ (row & 7u)) * 16u);
}
__device__ __forceinline__ void ldsm4(uint32_t& r0, uint32_t& r1, uint32_t& r2, uint32_t& r3, uint32_t addr) {
    asm volatile("ldmatrix.sync.aligned.m8n8.x4.shared.b16 {%0,%1,%2,%3}, [%4];"
        : "=r"(r0), "=r"(r1), "=r"(r2), "=r"(r3) : "r"(addr));
}
__device__ __forceinline__ void mma16816(float* d, const uint32_t* a, const uint32_t* b) {
    asm volatile(
        "mma.sync.aligned.m16n8k16.row.col.f32.f16.f16.f32 "
        "{%0,%1,%2,%3}, {%4,%5,%6,%7}, {%8,%9}, {%0,%1,%2,%3};"
        : "+f"(d[0]), "+f"(d[1]), "+f"(d[2]), "+f"(d[3])
        : "r"(a[0]), "r"(a[1]), "r"(a[2]), "r"(a[3]), "r"(b[0]), "r"(b[1]));
}

// ---------------- kernel 1: quantize x, compute beta ----------------
__device__ __forceinline__ uint32_t sign_h(float v) {
    return v >= 0.0f ? 0x3C00u : 0xBC00u;   // +1.0h / -1.0h
}

__global__ __launch_bounds__(128) void prep_x_kernel(const float* __restrict__ x) {
    int row = blockIdx.x;
    int t = threadIdx.x;  // 128 threads, 8 floats each
    const float4* xr = reinterpret_cast<const float4*>(x + (size_t)row * DD);
    float4 a = xr[2 * t];
    float4 b = xr[2 * t + 1];
    float s = fabsf(a.x) + fabsf(a.y) + fabsf(a.z) + fabsf(a.w)
            + fabsf(b.x) + fabsf(b.y) + fabsf(b.z) + fabsf(b.w);

    uint4 pk;
    pk.x = sign_h(a.x) | (sign_h(a.y) << 16);
    pk.y = sign_h(a.z) | (sign_h(a.w) << 16);
    pk.z = sign_h(b.x) | (sign_h(b.y) << 16);
    pk.w = sign_h(b.z) | (sign_h(b.w) << 16);
    reinterpret_cast<uint4*>(g_xq)[(size_t)row * 128 + t] = pk;

    #pragma unroll
    for (int o = 16; o > 0; o >>= 1) s += __shfl_xor_sync(0xFFFFFFFFu, s, o);
    __shared__ float ws[4];
    if ((t & 31) == 0) ws[t >> 5] = s;
    __syncthreads();
    if (t == 0) g_beta[row] = (ws[0] + ws[1] + ws[2] + ws[3]) * (1.0f / 1024.0f);
}

// ---------------- kernel 2: combined weight, transposed to [U, D] ----------------
__global__ __launch_bounds__(1024) void prep_w_kernel(
    const float* __restrict__ k0, const float* __restrict__ k1, const float* __restrict__ k2,
    const float* __restrict__ a0, const float* __restrict__ a1, const float* __restrict__ a2)
{
    __shared__ float tile[32][33];
    int tx = threadIdx.x, ty = threadIdx.y;
    int u = blockIdx.x * 32 + tx;
    int d = blockIdx.y * 32 + ty;
    float A0 = a0[u], A1 = a1[u], A2 = a2[u];
    size_t idx = (size_t)d * UU + u;
    float w = (k0[idx] >= 0.0f ? A0 : -A0)
            + (k1[idx] >= 0.0f ? A1 : -A1)
            + (k2[idx] >= 0.0f ? A2 : -A2);
    tile[ty][tx] = w;
    __syncthreads();
    int uo = blockIdx.x * 32 + ty;
    int dd = blockIdx.y * 32 + tx;
    g_wt[(size_t)uo * DD + dd] = __float2half(tile[tx][ty]);
}

// ---------------- kernel 3: HMMA GEMM (mma.sync) + beta-scale epilogue ----------------
// C[m, u] = sign(x)[m, :] . W_comb[:, u];  out = beta[m] * C
// CTA tile 256x128 (grid 1024 = 6.92 waves on 148 SMs), K-chunk 64,
// 4-stage cp.async pipeline, 16 warps (warp tile 64x32).
static constexpr int BM = 256, BN = 128, BK = 64;
static constexpr int STAGES = 4;
static constexpr int A_BYTES = BM * BK * 2;              // 32768
static constexpr int B_BYTES = BN * BK * 2;              // 16384
static constexpr int STG_BYTES = A_BYTES + B_BYTES;      // 49152
static constexpr int SMEM_TOTAL = STAGES * STG_BYTES;    // 196608
static constexpr int KITERS = DD / BK;                   // 16

__device__ __forceinline__ void load_stage(uint32_t sbase, int stage, int m0, int n0, int kb, int tid) {
    uint32_t sa  = sbase + (uint32_t)stage * STG_BYTES;
    uint32_t sbb = sa + A_BYTES;
    const char* gA = reinterpret_cast<const char*>(g_xq + (size_t)m0 * DD + kb);
    const char* gB = reinterpret_cast<const char*>(g_wt + (size_t)n0 * DD + kb);
    // A: 256 rows x 8 chunks of 16B = 2048 chunks, 512 threads -> 4 each
    #pragma unroll
    for (int i = 0; i < 4; i++) {
        int idx = tid + i * 512;
        uint32_t r = (uint32_t)idx >> 3, c = (uint32_t)idx & 7;
        cp16(sa + swz(r, c), gA + (size_t)r * (DD * 2) + c * 16);
    }
    // B: 128 rows x 8 chunks = 1024 chunks -> 2 each
    #pragma unroll
    for (int i = 0; i < 2; i++) {
        int idx = tid + i * 512;
        uint32_t r = (uint32_t)idx >> 3, c = (uint32_t)idx & 7;
        cp16(sbb + swz(r, c), gB + (size_t)r * (DD * 2) + c * 16);
    }
}

__global__ __launch_bounds__(512, 1) void gemm_kernel(float* __restrict__ out) {
    extern __shared__ char smem[];
    uint32_t sb = smem_u32(smem);
    int tid = threadIdx.x;
    int wid = tid >> 5, lane = tid & 31;
    int m0 = (int)(blockIdx.x >> 3) * BM;   // 128 m-tiles
    int n0 = (int)(blockIdx.x & 7) * BN;    // 8 n-tiles
    int wrow = (wid & 3) * 64;              // warp m-origin within CTA
    int wcol = (wid >> 2) * 32;             // warp n-origin within CTA

    // prologue: stages 0, 1, 2
    #pragma unroll
    for (int j = 0; j < 3; j++) {
        load_stage(sb, j, m0, n0, j * BK, tid);
        asm volatile("cp.async.commit_group;" ::: "memory");
    }

    float acc[4][4][4];
    #pragma unroll
    for (int i = 0; i < 4; i++)
        #pragma unroll
        for (int j = 0; j < 4; j++)
            #pragma unroll
            for (int k = 0; k < 4; k++) acc[i][j][k] = 0.0f;

    for (int it = 0; it < KITERS; ++it) {
        // group accounting: one commit per loop iter (possibly empty).
        // g_it completes data for iter it; wait<=2 with 3+it committed
        // guarantees g_0..g_it done.
        asm volatile("cp.async.wait_group 2;" ::: "memory");
        __syncthreads();
        if (it + 3 < KITERS)
            load_stage(sb, (it + 3) & 3, m0, n0, (it + 3) * BK, tid);
        asm volatile("cp.async.commit_group;" ::: "memory");

        uint32_t sa  = sb + (uint32_t)(it & 3) * STG_BYTES;
        uint32_t sbb = sa + A_BYTES;

        #pragma unroll
        for (int k16 = 0; k16 < 4; k16++) {
            uint32_t a[4][4], b[2][4];
            #pragma unroll
            for (int mb = 0; mb < 4; mb++) {
                uint32_t row = (uint32_t)(wrow + mb * 16 + (lane & 15));
                uint32_t ch  = (uint32_t)(k16 * 2 + (lane >> 4));
                ldsm4(a[mb][0], a[mb][1], a[mb][2], a[mb][3], sa + swz(row, ch));
            }
            #pragma unroll
            for (int nb16 = 0; nb16 < 2; nb16++) {
                uint32_t row = (uint32_t)(wcol + nb16 * 16 + (lane & 7) + (lane >> 4) * 8);
                uint32_t ch  = (uint32_t)(k16 * 2 + ((lane >> 3) & 1));
                ldsm4(b[nb16][0], b[nb16][1], b[nb16][2], b[nb16][3], sbb + swz(row, ch));
            }
            #pragma unroll
            for (int mb = 0; mb < 4; mb++)
                #pragma unroll
                for (int nb = 0; nb < 4; nb++)
                    mma16816(acc[mb][nb], a[mb], &b[nb >> 1][(nb & 1) * 2]);
        }
    }

    // epilogue: scale rows by beta and store
    int group = lane >> 2, t4 = lane & 3;
    #pragma unroll
    for (int mb = 0; mb < 4; mb++) {
        int r0 = m0 + wrow + mb * 16 + group;
        float b0 = g_beta[r0];
        float b1 = g_beta[r0 + 8];
        float* o0 = out + (size_t)r0 * UU + n0 + wcol + t4 * 2;
        float* o1 = o0 + (size_t)8 * UU;
        #pragma unroll
        for (int nb = 0; nb < 4; nb++) {
            float2 v0 = make_float2(acc[mb][nb][0] * b0, acc[mb][nb][1] * b0);
            float2 v1 = make_float2(acc[mb][nb][2] * b1, acc[mb][nb][3] * b1);
            *reinterpret_cast<float2*>(o0 + nb * 8) = v0;
            *reinterpret_cast<float2*>(o1 + nb * 8) = v1;
        }
    }
}

// ---------------- launch ----------------
extern "C" void kernel_launch(void* const* d_in, const int* in_sizes, int n_in,
                              void* d_out, int out_size) {
    const float* x  = (const float*)d_in[0];
    const float* k0 = (const float*)d_in[1];
    const float* k1 = (const float*)d_in[2];
    const float* k2 = (const float*)d_in[3];
    const float* a0 = (const float*)d_in[4];
    const float* a1 = (const float*)d_in[5];
    const float* a2 = (const float*)d_in[6];
    float* out = (float*)d_out;

    prep_x_kernel<<<TOK, 128>>>(x);
    prep_w_kernel<<<dim3(UU / 32, DD / 32), dim3(32, 32)>>>(k0, k1, k2, a0, a1, a2);

    cudaFuncSetAttribute(gemm_kernel, cudaFuncAttributeMaxDynamicSharedMemorySize, SMEM_TOTAL);
    gemm_kernel<<<(TOK / BM) * (UU / BN), 512, SMEM_TOTAL>>>(out);
}

// round 5
// speedup vs baseline: 1.0218x; 1.0200x over previous
#include <cuda_runtime.h>
#include <cuda_fp16.h>
#include <cstdint>

// Problem sizes (fixed by the dataset)
#define TOK 32768
#define DD  1024
#define UU  1024

// ---------------- scratch (device globals; no allocs allowed) ----------------
__device__ __align__(1024) __half g_xq[(size_t)TOK * DD];   // sign(x) as fp16 +/-1, [TOK, DD] row-major
__device__ __align__(1024) __half g_wt[(size_t)UU * DD];    // W_comb transposed: [U, D] K-major fp16
__device__ float g_beta[TOK];

// ---------------- helpers ----------------
__device__ __forceinline__ uint32_t smem_u32(const void* p) {
    uint32_t a;
    asm("{ .reg .u64 t; cvta.to.shared.u64 t, %1; cvt.u32.u64 %0, t; }" : "=r"(a) : "l"(p));
    return a;
}
__device__ __forceinline__ void cp16(uint32_t dst, const void* src) {
    asm volatile("cp.async.cg.shared.global [%0], [%1], 16;" :: "r"(dst), "l"(src));
}
__device__ __forceinline__ uint32_t swz(uint32_t row, uint32_t chunk) {
    // 128B rows, 8 x 16B chunks, XOR swizzle for conflict-free ldmatrix
    return row * 128u + ((chunk ^ (row & 7u)) * 16u);
}
__device__ __forceinline__ void ldsm4(uint32_t& r0, uint32_t& r1, uint32_t& r2, uint32_t& r3, uint32_t addr) {
    asm volatile("ldmatrix.sync.aligned.m8n8.x4.shared.b16 {%0,%1,%2,%3}, [%4];"
        : "=r"(r0), "=r"(r1), "=r"(r2), "=r"(r3) : "r"(addr));
}
__device__ __forceinline__ void mma16816(float* d, const uint32_t* a, const uint32_t* b) {
    asm volatile(
        "mma.sync.aligned.m16n8k16.row.col.f32.f16.f16.f32 "
        "{%0,%1,%2,%3}, {%4,%5,%6,%7}, {%8,%9}, {%0,%1,%2,%3};"
        : "+f"(d[0]), "+f"(d[1]), "+f"(d[2]), "+f"(d[3])
        : "r"(a[0]), "r"(a[1]), "r"(a[2]), "r"(a[3]), "r"(b[0]), "r"(b[1]));
}

__device__ __forceinline__ uint32_t sign_h(float v) {
    return v >= 0.0f ? 0x3C00u : 0xBC00u;   // +1.0h / -1.0h
}

// ---------------- kernel 1 (fused): quantize x + beta, and build W_comb^T ----------------
// blocks [0, TOK): prep_x (one token row per block, 128 threads)
// blocks [TOK, TOK + 1024): prep_w (one 32x32 tile per block, 128 threads)
__global__ __launch_bounds__(128) void prep_kernel(
    const float* __restrict__ x,
    const float* __restrict__ k0, const float* __restrict__ k1, const float* __restrict__ k2,
    const float* __restrict__ a0, const float* __restrict__ a1, const float* __restrict__ a2)
{
    int t = threadIdx.x;
    if (blockIdx.x < TOK) {
        int row = blockIdx.x;
        const float4* xr = reinterpret_cast<const float4*>(x + (size_t)row * DD);
        float4 a = xr[2 * t];
        float4 b = xr[2 * t + 1];
        float s = fabsf(a.x) + fabsf(a.y) + fabsf(a.z) + fabsf(a.w)
                + fabsf(b.x) + fabsf(b.y) + fabsf(b.z) + fabsf(b.w);

        uint4 pk;
        pk.x = sign_h(a.x) | (sign_h(a.y) << 16);
        pk.y = sign_h(a.z) | (sign_h(a.w) << 16);
        pk.z = sign_h(b.x) | (sign_h(b.y) << 16);
        pk.w = sign_h(b.z) | (sign_h(b.w) << 16);
        reinterpret_cast<uint4*>(g_xq)[(size_t)row * 128 + t] = pk;

        #pragma unroll
        for (int o = 16; o > 0; o >>= 1) s += __shfl_xor_sync(0xFFFFFFFFu, s, o);
        __shared__ float ws[4];
        if ((t & 31) == 0) ws[t >> 5] = s;
        __syncthreads();
        if (t == 0) g_beta[row] = (ws[0] + ws[1] + ws[2] + ws[3]) * (1.0f / 1024.0f);
    } else {
        // W_comb tile: 32 u-columns x 32 d-rows, transposed into g_wt [U, D]
        int b = blockIdx.x - TOK;
        int u0 = (b & 31) * 32;      // 32 u-tiles
        int d0 = (b >> 5) * 32;      // 32 d-tiles
        __shared__ float tile[32][33];
        int tx = t & 31;             // u lane
        int ty4 = t >> 5;            // 0..3, each covers 8 d-rows
        int u = u0 + tx;
        float A0 = a0[u], A1 = a1[u], A2 = a2[u];
        #pragma unroll
        for (int r = 0; r < 8; r++) {
            int d = d0 + ty4 * 8 + r;
            size_t idx = (size_t)d * UU + u;
            float w = (k0[idx] >= 0.0f ? A0 : -A0)
                    + (k1[idx] >= 0.0f ? A1 : -A1)
                    + (k2[idx] >= 0.0f ? A2 : -A2);
            tile[ty4 * 8 + r][tx] = w;
        }
        __syncthreads();
        // write transposed: g_wt[u, d], d contiguous (2B x 32 = 64B per row chunk)
        #pragma unroll
        for (int r = 0; r < 8; r++) {
            int uo = u0 + ty4 * 8 + r;
            int dd = d0 + tx;
            g_wt[(size_t)uo * DD + dd] = __float2half(tile[tx][ty4 * 8 + r]);
        }
    }
}

// ---------------- kernel 2: HMMA GEMM (mma.sync) + beta-scale epilogue ----------------
// C[m, u] = sign(x)[m, :] . W_comb[:, u];  out = beta[m] * C
// CTA tile 256x128, K-chunk 64, 4-stage cp.async pipeline, 16 warps (warp tile 64x32),
// register double-buffered fragments (LDSM for k16+1 overlaps MMA of k16).
static constexpr int BM = 256, BN = 128, BK = 64;
static constexpr int STAGES = 4;
static constexpr int A_BYTES = BM * BK * 2;              // 32768
static constexpr int B_BYTES = BN * BK * 2;              // 16384
static constexpr int STG_BYTES = A_BYTES + B_BYTES;      // 49152
static constexpr int SMEM_TOTAL = STAGES * STG_BYTES;    // 196608
static constexpr int KITERS = DD / BK;                   // 16

__device__ __forceinline__ void load_stage(uint32_t sbase, int stage, int m0, int n0, int kb, int tid) {
    uint32_t sa  = sbase + (uint32_t)stage * STG_BYTES;
    uint32_t sbb = sa + A_BYTES;
    const char* gA = reinterpret_cast<const char*>(g_xq + (size_t)m0 * DD + kb);
    const char* gB = reinterpret_cast<const char*>(g_wt + (size_t)n0 * DD + kb);
    #pragma unroll
    for (int i = 0; i < 4; i++) {
        int idx = tid + i * 512;
        uint32_t r = (uint32_t)idx >> 3, c = (uint32_t)idx & 7;
        cp16(sa + swz(r, c), gA + (size_t)r * (DD * 2) + c * 16);
    }
    #pragma unroll
    for (int i = 0; i < 2; i++) {
        int idx = tid + i * 512;
        uint32_t r = (uint32_t)idx >> 3, c = (uint32_t)idx & 7;
        cp16(sbb + swz(r, c), gB + (size_t)r * (DD * 2) + c * 16);
    }
}

__global__ __launch_bounds__(512, 1) void gemm_kernel(float* __restrict__ out) {
    extern __shared__ char smem[];
    uint32_t sb = smem_u32(smem);
    int tid = threadIdx.x;
    int wid = tid >> 5, lane = tid & 31;
    int m0 = (int)(blockIdx.x >> 3) * BM;
    int n0 = (int)(blockIdx.x & 7) * BN;
    int wrow = (wid & 3) * 64;
    int wcol = (wid >> 2) * 32;

    // per-warp ldmatrix source addresses (k16-dependent part added later)
    uint32_t a_row = (uint32_t)(wrow + (lane & 15));         // + mb*16
    uint32_t a_ch0 = (uint32_t)(lane >> 4);                  // + k16*2
    uint32_t b_row = (uint32_t)(wcol + (lane & 7) + (lane >> 4) * 8);  // + nb16*16
    uint32_t b_ch0 = (uint32_t)((lane >> 3) & 1);            // + k16*2

    #pragma unroll
    for (int j = 0; j < 3; j++) {
        load_stage(sb, j, m0, n0, j * BK, tid);
        asm volatile("cp.async.commit_group;" ::: "memory");
    }

    float acc[4][4][4];
    #pragma unroll
    for (int i = 0; i < 4; i++)
        #pragma unroll
        for (int j = 0; j < 4; j++)
            #pragma unroll
            for (int k = 0; k < 4; k++) acc[i][j][k] = 0.0f;

    uint32_t a[2][4][4], b[2][2][4];

    for (int it = 0; it < KITERS; ++it) {
        asm volatile("cp.async.wait_group 2;" ::: "memory");
        __syncthreads();
        if (it + 3 < KITERS)
            load_stage(sb, (it + 3) & 3, m0, n0, (it + 3) * BK, tid);
        asm volatile("cp.async.commit_group;" ::: "memory");

        uint32_t sa  = sb + (uint32_t)(it & 3) * STG_BYTES;
        uint32_t sbb = sa + A_BYTES;

        // preload k16 = 0 into buffer 0
        #pragma unroll
        for (int mb = 0; mb < 4; mb++)
            ldsm4(a[0][mb][0], a[0][mb][1], a[0][mb][2], a[0][mb][3],
                  sa + swz(a_row + mb * 16, a_ch0));
        #pragma unroll
        for (int nb16 = 0; nb16 < 2; nb16++)
            ldsm4(b[0][nb16][0], b[0][nb16][1], b[0][nb16][2], b[0][nb16][3],
                  sbb + swz(b_row + nb16 * 16, b_ch0));

        #pragma unroll
        for (int k16 = 0; k16 < 4; k16++) {
            int cur = k16 & 1, nxt = cur ^ 1;
            if (k16 < 3) {
                uint32_t ach = a_ch0 + (uint32_t)(k16 + 1) * 2;
                uint32_t bch = b_ch0 + (uint32_t)(k16 + 1) * 2;
                #pragma unroll
                for (int mb = 0; mb < 4; mb++)
                    ldsm4(a[nxt][mb][0], a[nxt][mb][1], a[nxt][mb][2], a[nxt][mb][3],
                          sa + swz(a_row + mb * 16, ach));
                #pragma unroll
                for (int nb16 = 0; nb16 < 2; nb16++)
                    ldsm4(b[nxt][nb16][0], b[nxt][nb16][1], b[nxt][nb16][2], b[nxt][nb16][3],
                          sbb + swz(b_row + nb16 * 16, bch));
            }
            #pragma unroll
            for (int mb = 0; mb < 4; mb++)
                #pragma unroll
                for (int nb = 0; nb < 4; nb++)
                    mma16816(acc[mb][nb], a[cur][mb], &b[cur][nb >> 1][(nb & 1) * 2]);
        }
    }

    // epilogue: scale rows by beta and store
    int group = lane >> 2, t4 = lane & 3;
    #pragma unroll
    for (int mb = 0; mb < 4; mb++) {
        int r0 = m0 + wrow + mb * 16 + group;
        float b0 = g_beta[r0];
        float b1 = g_beta[r0 + 8];
        float* o0 = out + (size_t)r0 * UU + n0 + wcol + t4 * 2;
        float* o1 = o0 + (size_t)8 * UU;
        #pragma unroll
        for (int nb = 0; nb < 4; nb++) {
            float2 v0 = make_float2(acc[mb][nb][0] * b0, acc[mb][nb][1] * b0);
            float2 v1 = make_float2(acc[mb][nb][2] * b1, acc[mb][nb][3] * b1);
            *reinterpret_cast<float2*>(o0 + nb * 8) = v0;
            *reinterpret_cast<float2*>(o1 + nb * 8) = v1;
        }
    }
}

// ---------------- launch ----------------
extern "C" void kernel_launch(void* const* d_in, const int* in_sizes, int n_in,
                              void* d_out, int out_size) {
    const float* x  = (const float*)d_in[0];
    const float* k0 = (const float*)d_in[1];
    const float* k1 = (const float*)d_in[2];
    const float* k2 = (const float*)d_in[3];
    const float* a0 = (const float*)d_in[4];
    const float* a1 = (const float*)d_in[5];
    const float* a2 = (const float*)d_in[6];
    float* out = (float*)d_out;

    prep_kernel<<<TOK + 1024, 128>>>(x, k0, k1, k2, a0, a1, a2);

    cudaFuncSetAttribute(gemm_kernel, cudaFuncAttributeMaxDynamicSharedMemorySize, SMEM_TOTAL);
    gemm_kernel<<<(TOK / BM) * (UU / BN), 512, SMEM_TOTAL>>>(out);
}

// round 6
// speedup vs baseline: 1.0992x; 1.0757x over previous
#include <cuda_runtime.h>
#include <cuda_fp16.h>
#include <cstdint>

// Problem sizes (fixed by the dataset)
#define TOK 32768
#define DD  1024
#define UU  1024

// ---------------- scratch (device globals; no allocs allowed) ----------------
__device__ __align__(1024) __half g_xq[(size_t)TOK * DD];   // sign(x) as fp16 +/-1, [TOK, DD] row-major
__device__ __align__(1024) __half g_wt[(size_t)UU * DD];    // W_comb transposed: [U, D] K-major fp16
__device__ float g_beta[TOK];

// ---------------- helpers ----------------
__device__ __forceinline__ uint32_t smem_u32(const void* p) {
    uint32_t a;
    asm("{ .reg .u64 t; cvta.to.shared.u64 t, %1; cvt.u32.u64 %0, t; }" : "=r"(a) : "l"(p));
    return a;
}
__device__ __forceinline__ void cp16(uint32_t dst, const void* src) {
    asm volatile("cp.async.cg.shared.global [%0], [%1], 16;" :: "r"(dst), "l"(src));
}
__device__ __forceinline__ uint32_t swz(uint32_t row, uint32_t chunk) {
    // 128B rows, 8 x 16B chunks, XOR swizzle for conflict-free ldmatrix
    return row * 128u + ((chunk ^ (row & 7u)) * 16u);
}
__device__ __forceinline__ void ldsm4(uint32_t& r0, uint32_t& r1, uint32_t& r2, uint32_t& r3, uint32_t addr) {
    asm volatile("ldmatrix.sync.aligned.m8n8.x4.shared.b16 {%0,%1,%2,%3}, [%4];"
        : "=r"(r0), "=r"(r1), "=r"(r2), "=r"(r3) : "r"(addr));
}
__device__ __forceinline__ void mma16816(float* d, const uint32_t* a, const uint32_t* b) {
    asm volatile(
        "mma.sync.aligned.m16n8k16.row.col.f32.f16.f16.f32 "
        "{%0,%1,%2,%3}, {%4,%5,%6,%7}, {%8,%9}, {%0,%1,%2,%3};"
        : "+f"(d[0]), "+f"(d[1]), "+f"(d[2]), "+f"(d[3])
        : "r"(a[0]), "r"(a[1]), "r"(a[2]), "r"(a[3]), "r"(b[0]), "r"(b[1]));
}

__device__ __forceinline__ uint32_t sign_h(float v) {
    return v >= 0.0f ? 0x3C00u : 0xBC00u;   // +1.0h / -1.0h
}

// ---------------- kernel 1 (fused): quantize x + beta, and build W_comb^T ----------------
__global__ __launch_bounds__(128) void prep_kernel(
    const float* __restrict__ x,
    const float* __restrict__ k0, const float* __restrict__ k1, const float* __restrict__ k2,
    const float* __restrict__ a0, const float* __restrict__ a1, const float* __restrict__ a2)
{
    int t = threadIdx.x;
    if (blockIdx.x < TOK) {
        int row = blockIdx.x;
        const float4* xr = reinterpret_cast<const float4*>(x + (size_t)row * DD);
        float4 a = xr[2 * t];
        float4 b = xr[2 * t + 1];
        float s = fabsf(a.x) + fabsf(a.y) + fabsf(a.z) + fabsf(a.w)
                + fabsf(b.x) + fabsf(b.y) + fabsf(b.z) + fabsf(b.w);

        uint4 pk;
        pk.x = sign_h(a.x) | (sign_h(a.y) << 16);
        pk.y = sign_h(a.z) | (sign_h(a.w) << 16);
        pk.z = sign_h(b.x) | (sign_h(b.y) << 16);
        pk.w = sign_h(b.z) | (sign_h(b.w) << 16);
        reinterpret_cast<uint4*>(g_xq)[(size_t)row * 128 + t] = pk;

        #pragma unroll
        for (int o = 16; o > 0; o >>= 1) s += __shfl_xor_sync(0xFFFFFFFFu, s, o);
        __shared__ float ws[4];
        if ((t & 31) == 0) ws[t >> 5] = s;
        __syncthreads();
        if (t == 0) g_beta[row] = (ws[0] + ws[1] + ws[2] + ws[3]) * (1.0f / 1024.0f);
    } else {
        // W_comb tile: 32 u-columns x 32 d-rows, transposed into g_wt [U, D]
        int b = blockIdx.x - TOK;
        int u0 = (b & 31) * 32;
        int d0 = (b >> 5) * 32;
        __shared__ float tile[32][33];
        int tx = t & 31;
        int ty4 = t >> 5;
        int u = u0 + tx;
        float A0 = a0[u], A1 = a1[u], A2 = a2[u];
        #pragma unroll
        for (int r = 0; r < 8; r++) {
            int d = d0 + ty4 * 8 + r;
            size_t idx = (size_t)d * UU + u;
            float w = (k0[idx] >= 0.0f ? A0 : -A0)
                    + (k1[idx] >= 0.0f ? A1 : -A1)
                    + (k2[idx] >= 0.0f ? A2 : -A2);
            tile[ty4 * 8 + r][tx] = w;
        }
        __syncthreads();
        #pragma unroll
        for (int r = 0; r < 8; r++) {
            int uo = u0 + ty4 * 8 + r;
            int dd = d0 + tx;
            g_wt[(size_t)uo * DD + dd] = __float2half(tile[tx][ty4 * 8 + r]);
        }
    }
}

// ---------------- kernel 2: HMMA GEMM, 2 CTAs/SM for cross-CTA overlap ----------------
// CTA tile 128x128, 256 threads (8 warps, warp tile 32x64), K-chunk 64,
// 3-stage cp.async pipeline (96 KB smem/CTA), 2 CTAs resident per SM.
static constexpr int BM = 128, BN = 128, BK = 64;
static constexpr int STAGES = 3;
static constexpr int A_BYTES = BM * BK * 2;              // 16384
static constexpr int B_BYTES = BN * BK * 2;              // 16384
static constexpr int STG_BYTES = A_BYTES + B_BYTES;      // 32768
static constexpr int SMEM_TOTAL = STAGES * STG_BYTES;    // 98304
static constexpr int KITERS = DD / BK;                   // 16

__device__ __forceinline__ void load_stage(uint32_t sbase, int stage, int m0, int n0, int kb, int tid) {
    uint32_t sa  = sbase + (uint32_t)stage * STG_BYTES;
    uint32_t sbb = sa + A_BYTES;
    const char* gA = reinterpret_cast<const char*>(g_xq + (size_t)m0 * DD + kb);
    const char* gB = reinterpret_cast<const char*>(g_wt + (size_t)n0 * DD + kb);
    // A: 128 rows x 8 chunks of 16B = 1024 chunks, 256 threads -> 4 each
    #pragma unroll
    for (int i = 0; i < 4; i++) {
        int idx = tid + i * 256;
        uint32_t r = (uint32_t)idx >> 3, c = (uint32_t)idx & 7;
        cp16(sa + swz(r, c), gA + (size_t)r * (DD * 2) + c * 16);
    }
    // B: 128 rows x 8 chunks = 1024 chunks -> 4 each
    #pragma unroll
    for (int i = 0; i < 4; i++) {
        int idx = tid + i * 256;
        uint32_t r = (uint32_t)idx >> 3, c = (uint32_t)idx & 7;
        cp16(sbb + swz(r, c), gB + (size_t)r * (DD * 2) + c * 16);
    }
}

__global__ __launch_bounds__(256, 2) void gemm_kernel(float* __restrict__ out) {
    extern __shared__ char smem[];
    uint32_t sb = smem_u32(smem);
    int tid = threadIdx.x;
    int wid = tid >> 5, lane = tid & 31;
    int m0 = (int)(blockIdx.x >> 3) * BM;   // 256 m-tiles
    int n0 = (int)(blockIdx.x & 7) * BN;    // 8 n-tiles
    int wrow = (wid & 3) * 32;              // 4 m-warps x 32 rows
    int wcol = (wid >> 2) * 64;             // 2 n-warps x 64 cols

    uint32_t a_row = (uint32_t)(wrow + (lane & 15));
    uint32_t a_ch0 = (uint32_t)(lane >> 4);
    uint32_t b_row = (uint32_t)(wcol + (lane & 7) + (lane >> 4) * 8);
    uint32_t b_ch0 = (uint32_t)((lane >> 3) & 1);

    // prologue: stages 0, 1
    #pragma unroll
    for (int j = 0; j < 2; j++) {
        load_stage(sb, j, m0, n0, j * BK, tid);
        asm volatile("cp.async.commit_group;" ::: "memory");
    }

    float acc[2][8][4];
    #pragma unroll
    for (int i = 0; i < 2; i++)
        #pragma unroll
        for (int j = 0; j < 8; j++)
            #pragma unroll
            for (int k = 0; k < 4; k++) acc[i][j][k] = 0.0f;

    uint32_t a[2][2][4], b[2][4][4];

    for (int it = 0; it < KITERS; ++it) {
        // one commit per iter (possibly empty); at iter it there are 2+it commits,
        // wait<=1 leaves the newest outstanding -> groups 0..it done -> stage it ready.
        asm volatile("cp.async.wait_group 1;" ::: "memory");
        __syncthreads();
        if (it + 2 < KITERS)
            load_stage(sb, (it + 2) % STAGES, m0, n0, (it + 2) * BK, tid);
        asm volatile("cp.async.commit_group;" ::: "memory");

        uint32_t sa  = sb + (uint32_t)(it % STAGES) * STG_BYTES;
        uint32_t sbb = sa + A_BYTES;

        // preload k16 = 0 into buffer 0
        #pragma unroll
        for (int mb = 0; mb < 2; mb++)
            ldsm4(a[0][mb][0], a[0][mb][1], a[0][mb][2], a[0][mb][3],
                  sa + swz(a_row + mb * 16, a_ch0));
        #pragma unroll
        for (int nb16 = 0; nb16 < 4; nb16++)
            ldsm4(b[0][nb16][0], b[0][nb16][1], b[0][nb16][2], b[0][nb16][3],
                  sbb + swz(b_row + nb16 * 16, b_ch0));

        #pragma unroll
        for (int k16 = 0; k16 < 4; k16++) {
            int cur = k16 & 1, nxt = cur ^ 1;
            if (k16 < 3) {
                uint32_t ach = a_ch0 + (uint32_t)(k16 + 1) * 2;
                uint32_t bch = b_ch0 + (uint32_t)(k16 + 1) * 2;
                #pragma unroll
                for (int mb = 0; mb < 2; mb++)
                    ldsm4(a[nxt][mb][0], a[nxt][mb][1], a[nxt][mb][2], a[nxt][mb][3],
                          sa + swz(a_row + mb * 16, ach));
                #pragma unroll
                for (int nb16 = 0; nb16 < 4; nb16++)
                    ldsm4(b[nxt][nb16][0], b[nxt][nb16][1], b[nxt][nb16][2], b[nxt][nb16][3],
                          sbb + swz(b_row + nb16 * 16, bch));
            }
            #pragma unroll
            for (int mb = 0; mb < 2; mb++)
                #pragma unroll
                for (int nb = 0; nb < 8; nb++)
                    mma16816(acc[mb][nb], a[cur][mb], &b[cur][nb >> 1][(nb & 1) * 2]);
        }
    }

    // epilogue: scale rows by beta and store
    int group = lane >> 2, t4 = lane & 3;
    #pragma unroll
    for (int mb = 0; mb < 2; mb++) {
        int r0 = m0 + wrow + mb * 16 + group;
        float b0 = g_beta[r0];
        float b1 = g_beta[r0 + 8];
        float* o0 = out + (size_t)r0 * UU + n0 + wcol + t4 * 2;
        float* o1 = o0 + (size_t)8 * UU;
        #pragma unroll
        for (int nb = 0; nb < 8; nb++) {
            float2 v0 = make_float2(acc[mb][nb][0] * b0, acc[mb][nb][1] * b0);
            float2 v1 = make_float2(acc[mb][nb][2] * b1, acc[mb][nb][3] * b1);
            *reinterpret_cast<float2*>(o0 + nb * 8) = v0;
            *reinterpret_cast<float2*>(o1 + nb * 8) = v1;
        }
    }
}

// ---------------- launch ----------------
extern "C" void kernel_launch(void* const* d_in, const int* in_sizes, int n_in,
                              void* d_out, int out_size) {
    const float* x  = (const float*)d_in[0];
    const float* k0 = (const float*)d_in[1];
    const float* k1 = (const float*)d_in[2];
    const float* k2 = (const float*)d_in[3];
    const float* a0 = (const float*)d_in[4];
    const float* a1 = (const float*)d_in[5];
    const float* a2 = (const float*)d_in[6];
    float* out = (float*)d_out;

    prep_kernel<<<TOK + 1024, 128>>>(x, k0, k1, k2, a0, a1, a2);

    cudaFuncSetAttribute(gemm_kernel, cudaFuncAttributeMaxDynamicSharedMemorySize, SMEM_TOTAL);
    gemm_kernel<<<(TOK / BM) * (UU / BN), 256, SMEM_TOTAL>>>(out);
}